// round 16
// baseline (speedup 1.0000x reference)
#include <cuda_runtime.h>
#include <cstdint>

#define NB   32
#define NH   64
#define NW   64
#define HO   62
#define WO   62
#define NPB  (HO*WO)            // 3844

// A: [cblk 4][kh 3][kw 3][ocb 8][perm 128] fp16x2 (lane-major permuted layout)
__device__ __align__(16) uint32_t g_a16[36*1024];            // 147.5 KB

// ---- SMEM geometry (words per buffer) ----
#define AWRD  9216              // 9 (kh,kw) tiles x 1024 words
#define BROWW 72                // B words per c2 row (68 data + 4 pad)
#define BWRD  (4*8*BROWW)       // 2304 : [row 4][c2 8][72]
#define STW   (AWRD + BWRD)     // 11520
#define NBUF  2
#define SMEMB (NBUF*STW*4)      // 92160 B

// ---------------- PTX helpers ----------------
__device__ __forceinline__ uint32_t cvta_s(const void* p) {
    uint32_t a;
    asm("{ .reg .u64 t; cvta.to.shared.u64 t, %1; cvt.u32.u64 %0, t; }" : "=r"(a) : "l"(p));
    return a;
}
__device__ __forceinline__ uint32_t pack_h2(float even, float odd) {
    uint32_t d;
    asm("cvt.rn.f16x2.f32 %0, %1, %2;" : "=r"(d) : "f"(odd), "f"(even));  // lo=even, hi=odd
    return d;
}
__device__ __forceinline__ uint32_t lds32(uint32_t addr) {
    uint32_t v;
    asm volatile("ld.shared.b32 %0,[%1];" : "=r"(v) : "r"(addr));
    return v;
}
__device__ __forceinline__ uint4 lds128(uint32_t addr) {
    uint4 v;
    asm volatile("ld.shared.v4.b32 {%0,%1,%2,%3},[%4];"
                 : "=r"(v.x), "=r"(v.y), "=r"(v.z), "=r"(v.w) : "r"(addr));
    return v;
}
__device__ __forceinline__ void sts128(uint32_t addr, uint4 v) {
    asm volatile("st.shared.v4.b32 [%0],{%1,%2,%3,%4};"
                 :: "r"(addr), "r"(v.x), "r"(v.y), "r"(v.z), "r"(v.w) : "memory");
}
#define CP_A16(dst, src) asm volatile("cp.async.cg.shared.global [%0],[%1],16;" :: "r"(dst), "l"(src))
#define CP_COMMIT()      asm volatile("cp.async.commit_group;" ::: "memory")
#define CP_WAIT0()       asm volatile("cp.async.wait_group 0;" ::: "memory")

__device__ __forceinline__ void mma_f16(float* c, const uint32_t* a, uint32_t b0, uint32_t b1) {
    asm volatile(
        "mma.sync.aligned.m16n8k16.row.col.f32.f16.f16.f32 "
        "{%0,%1,%2,%3},{%4,%5,%6,%7},{%8,%9},{%0,%1,%2,%3};"
        : "+f"(c[0]), "+f"(c[1]), "+f"(c[2]), "+f"(c[3])
        : "r"(a[0]), "r"(a[1]), "r"(a[2]), "r"(a[3]), "r"(b0), "r"(b1));
}

// ---------------- prep kernel (weights only) ----------------
// A tile (cblk,kh,kw) = 1024 words; within: ocb = (oc>>4) block of 128 words,
// permuted so lane l's four fragment words sit at l*4..l*4+3.
__global__ void prep_w(const float* __restrict__ w) {
    int idx = blockIdx.x * 256 + threadIdx.x;    // 36864 (cblk,kh,kw,oc,slot)
    int slot = idx & 7;
    int oc   = (idx >> 3) & 127;
    int t    = idx >> 10;          // 0..35
    int cblk = t / 9;
    int r9   = t - cblk * 9;
    int kh   = r9 / 3;
    int kw   = r9 - kh * 3;
    int off  = kh * 3 + kw;
    int p    = (slot >> 1) + 4 * (slot & 1);
    int ce   = cblk * 16 + 2 * p;
    uint32_t val = pack_h2(w[oc * 576 + ce * 9 + off], w[oc * 576 + (ce + 1) * 9 + off]);

    int ocb = oc >> 4;
    int ocr = oc & 15;
    int r8  = ocr & 7;
    int hi  = ocr >> 3;
    int n   = (r8 * 4 + (slot >> 1)) * 4 + (slot & 1) * 2 + hi;
    g_a16[t * 1024 + ocb * 128 + n] = val;
}

// ---------------- main kernel ----------------
// CTA: 128 oc x 2 out-rows x 64 wo; 4 stages (one per cblk, K=144).
__global__ __launch_bounds__(256, 2) void conv_main(const float* __restrict__ x,
                                                    float* __restrict__ out) {
    extern __shared__ __align__(16) uint32_t sm[];

    const int tid  = threadIdx.x;
    const int lane = tid & 31;
    const int warp = tid >> 5;
    const int wm   = warp >> 2;        // 0..1 : oc half
    const int wn   = warp & 3;
    const int rW   = wn >> 1;          // output row within pair
    const int cW   = (wn & 1) * 32;    // wo base

    const int b   = blockIdx.y;
    const int ho0 = blockIdx.x * 2;

    const uint32_t smem_b = cvta_s(sm);

    // ---- B staging descriptors: 544 x 16B ops ----
    const float* bs[3]; uint32_t bdw[3]; bool bact[3];
    #pragma unroll
    for (int j = 0; j < 3; ++j) {
        int e = tid + j * 256;
        bact[j] = (e < 544);
        int ee = bact[j] ? e : 0;
        int r  = ee / 17, q = ee - r * 17;
        int qe = (q > 15) ? 15 : q;
        int c2 = r >> 2, row = r & 3;
        bs[j]  = x + ((size_t)(b * 64 + 2 * c2)) * 4096 + (ho0 + row) * 64 + 4 * qe;
        bdw[j] = (uint32_t)(AWRD + row * (8 * BROWW) + c2 * BROWW + 4 * q);
    }

    float acc[4][4][4];
    #pragma unroll
    for (int mi = 0; mi < 4; ++mi)
        #pragma unroll
        for (int ni = 0; ni < 4; ++ni)
            #pragma unroll
            for (int q = 0; q < 4; ++q) acc[mi][ni][q] = 0.0f;

    const uint32_t a_fw = (uint32_t)(wm * 512 + lane * 4) * 4;          // 16B aligned
    const uint32_t b_fw = (uint32_t)(AWRD + (lane & 3) * BROWW + cW + (lane >> 2)) * 4;

    auto issueA = [&](int cblk, uint32_t bufw) {
        const uint4* asrc = (const uint4*)(g_a16 + cblk * AWRD) + tid;
        uint32_t adst = smem_b + bufw * 4 + (uint32_t)tid * 16;
        #pragma unroll
        for (int j = 0; j < 9; ++j)
            CP_A16(adst + (uint32_t)j * 4096, asrc + j * 256);
        CP_COMMIT();
    };

    // ---- prologue ----
    issueA(0, 0);
    #pragma unroll
    for (int j = 0; j < 3; ++j) {
        if (bact[j]) {
            float4 e = *(const float4*)(bs[j]);
            float4 o = *(const float4*)(bs[j] + 4096);
            uint4 v;
            v.x = pack_h2(e.x, o.x); v.y = pack_h2(e.y, o.y);
            v.z = pack_h2(e.z, o.z); v.w = pack_h2(e.w, o.w);
            sts128(smem_b + bdw[j] * 4, v);
        }
    }

    uint32_t cbuf = 0;

    #pragma unroll 1
    for (int s = 0; s < 4; ++s) {
        CP_WAIT0();
        __syncthreads();

        const uint32_t nbuf = cbuf ^ STW;
        const bool haveNext = (s + 1 < 4);
        if (haveNext) issueA(s + 1, nbuf);

        const uint32_t nso = (uint32_t)((s + 1) * 16 * 4096);

        const uint32_t abase0 = smem_b + cbuf * 4 + a_fw;
        const uint32_t bbaseS = smem_b + cbuf * 4 + b_fw;

        // fragment loader for flat iteration t (wm-staggered traversal)
        auto loadFrag = [&](int t, uint32_t* af, uint32_t* bf) {
            const int tt = wm ? (8 - t) : t;
            const int kh = tt / 3;
            const int kw = tt - kh * 3;
            const uint32_t brow = bbaseS
                + ((uint32_t)((rW + kh) * (8 * BROWW)) + (uint32_t)kw) * 4;
            #pragma unroll
            for (int ni = 0; ni < 4; ++ni) {
                bf[ni * 2 + 0] = lds32(brow + (uint32_t)ni * 32);
                bf[ni * 2 + 1] = lds32(brow + (uint32_t)ni * 32 + 4 * BROWW * 4);
            }
            const uint32_t abase = abase0 + (uint32_t)(kh * 3 + kw) * 4096;
            #pragma unroll
            for (int mi = 0; mi < 4; ++mi) {
                uint4 a4 = lds128(abase + (uint32_t)mi * 512);
                af[mi * 4 + 0] = a4.x; af[mi * 4 + 1] = a4.y;
                af[mi * 4 + 2] = a4.z; af[mi * 4 + 3] = a4.w;
            }
        };

        uint32_t afb[2][16], bfb[2][8];
        loadFrag(0, afb[0], bfb[0]);

        float4 e, o;
        #pragma unroll
        for (int t = 0; t < 9; ++t) {
            const int cur = t & 1, nxt = cur ^ 1;
            const int ki = t / 3;
            const int ph = t - ki * 3;

            // staging LDG for next stage, one op per kh-triple
            const bool doB = haveNext && bact[ki];
            if (ph == 0 && doB) {
                e = *(const float4*)(bs[ki] + nso);
                o = *(const float4*)(bs[ki] + nso + 4096);
            }

            // prefetch fragments for t+1
            if (t < 8) loadFrag(t + 1, afb[nxt], bfb[nxt]);

            // HMMA burst for t
            #pragma unroll
            for (int mi = 0; mi < 4; ++mi)
                #pragma unroll
                for (int ni = 0; ni < 4; ++ni)
                    mma_f16(acc[mi][ni], &afb[cur][mi * 4],
                            bfb[cur][ni * 2], bfb[cur][ni * 2 + 1]);

            // staging STS at end of kh-triple
            if (ph == 2 && doB) {
                uint4 v;
                v.x = pack_h2(e.x, o.x); v.y = pack_h2(e.y, o.y);
                v.z = pack_h2(e.z, o.z); v.w = pack_h2(e.w, o.w);
                sts128(smem_b + (nbuf + bdw[ki]) * 4, v);
            }
        }

        cbuf = nbuf;
    }

    // ---- epilogue ----
    const int orow = ho0 + rW;
    #pragma unroll
    for (int mi = 0; mi < 4; ++mi) {
        #pragma unroll
        for (int ni = 0; ni < 4; ++ni) {
            const int ocr = wm * 64 + mi * 16 + (lane >> 2);
            const int wo  = cW + ni * 8 + 2 * (lane & 3);
            if (wo < WO) {
                const size_t base = (size_t)orow * WO + wo;
                float* p0 = out + ((size_t)ocr * NB + b) * NPB + base;
                *(float2*)p0 = make_float2(acc[mi][ni][0], acc[mi][ni][1]);
                float* p1 = out + ((size_t)(ocr + 8) * NB + b) * NPB + base;
                *(float2*)p1 = make_float2(acc[mi][ni][2], acc[mi][ni][3]);
            }
        }
    }
}

// ---------------- launch ----------------
extern "C" void kernel_launch(void* const* d_in, const int* in_sizes, int n_in,
                              void* d_out, int out_size) {
    const float* x = (const float*)d_in[0];
    const float* w = (const float*)d_in[1];
    float* out = (float*)d_out;

    cudaFuncSetAttribute(conv_main, cudaFuncAttributeMaxDynamicSharedMemorySize, SMEMB);

    prep_w<<<144, 256>>>(w);
    conv_main<<<dim3(31, NB), 256, SMEMB>>>(x, out);
}